// round 15
// baseline (speedup 1.0000x reference)
#include <cuda_runtime.h>
#include <cstdint>

// Problem constants
constexpr int B_ = 8, E_ = 16, H_ = 256, W_ = 256;
constexpr int HW    = H_ * W_;          // 65536
constexpr int NPIX  = B_ * HW;          // 524288
constexpr int TPB   = 256;
constexpr int SPX   = 256;              // pixels per CTA (one per thread)
constexpr int NCTA  = NPIX / SPX;       // 2048

constexpr int SLICE_BYTES = SPX * 4;             // 1024
constexpr int STAGE_BYTES = E_ * SLICE_BYTES;    // 16384 (fore only; obs via LDG)

// Deterministic fixed-point global accumulator.
__device__ unsigned long long g_acc;
__device__ unsigned int       g_tick;
constexpr double FPSCALE = 4294967296.0;  // 2^32

__device__ __forceinline__ uint32_t smem_u32(const void* p) {
    uint32_t a;
    asm("{ .reg .u64 t; cvta.to.shared.u64 t, %1; cvt.u32.u64 %0, t; }" : "=r"(a) : "l"(p));
    return a;
}
__device__ __forceinline__ void mbar_init(uint32_t a, uint32_t cnt) {
    asm volatile("mbarrier.init.shared.b64 [%0], %1;" :: "r"(a), "r"(cnt) : "memory");
}
__device__ __forceinline__ void mbar_expect_tx(uint32_t a, uint32_t bytes) {
    asm volatile("mbarrier.arrive.expect_tx.shared.b64 _, [%0], %1;" :: "r"(a), "r"(bytes) : "memory");
}
__device__ __forceinline__ void bulk_g2s(uint32_t dst, const void* src, uint32_t bytes, uint32_t mbar) {
    asm volatile(
        "cp.async.bulk.shared::cluster.global.mbarrier::complete_tx::bytes [%0], [%1], %2, [%3];"
        :: "r"(dst), "l"(src), "r"(bytes), "r"(mbar) : "memory");
}
__device__ __forceinline__ void mbar_wait_parity(uint32_t mbar, uint32_t parity) {
    asm volatile(
        "{\n\t"
        ".reg .pred P;\n\t"
        "WL_%=:\n\t"
        "mbarrier.try_wait.parity.acquire.cta.shared::cta.b64 P, [%0], %1, 0x989680;\n\t"
        "@P bra.uni WD_%=;\n\t"
        "bra.uni WL_%=;\n\t"
        "WD_%=:\n\t"
        "}" :: "r"(mbar), "r"(parity) : "memory");
}

__device__ __forceinline__ void cmpswap(float& a, float& b) {
    const float lo = fminf(a, b);
    const float hi = fmaxf(a, b);
    a = lo; b = hi;
}

__global__ void __launch_bounds__(TPB, 8)
crps_tma2_kernel(const float* __restrict__ fore, const float* __restrict__ obs,
                 float* __restrict__ out) {
    // Static SMEM: 16 fore slices + mbarrier.  ~16.5KB -> 8 CTAs/SM (reg-capped).
    __shared__ alignas(128) float sf[E_ * SPX];
    __shared__ alignas(16)  unsigned long long mbar_storage;

    const uint32_t mb    = smem_u32(&mbar_storage);
    const uint32_t sbase = smem_u32(sf);
    const int tid = threadIdx.x;
    const int g0  = blockIdx.x * SPX;

    // 1) init barrier (one thread), make it visible to the async proxy.
    if (tid == 0) {
        mbar_init(mb, 1);
        asm volatile("fence.proxy.async.shared::cta;" ::: "memory");
    }
    // 2) ALL threads must see the initialized barrier before anyone waits on it.
    __syncthreads();

    // 3) issue the DMA (one thread).
    if (tid == 0) {
        const int b = g0 >> 16;          // batch index (tile never crosses batches)
        const int p = g0 & (HW - 1);
        const float* fb = fore + ((size_t)b * E_) * HW + p;
        mbar_expect_tx(mb, STAGE_BYTES);
#pragma unroll
        for (int e = 0; e < E_; e++)
            bulk_g2s(sbase + e * SLICE_BYTES, fb + (size_t)e * HW, SLICE_BYTES, mb);
    }

    // obs via plain coalesced LDG, overlapped with the TMA.
    const float o = __ldg(obs + g0 + tid);

    mbar_wait_parity(mb, 0);

    float f[E_];
#pragma unroll
    for (int e = 0; e < E_; e++) f[e] = sf[e * SPX + tid];

    // term1 numerator: tree sum of |f_e - o|
    float a0 = fabsf(f[0]-o)+fabsf(f[1]-o),  a1 = fabsf(f[2]-o)+fabsf(f[3]-o);
    float a2 = fabsf(f[4]-o)+fabsf(f[5]-o),  a3 = fabsf(f[6]-o)+fabsf(f[7]-o);
    float a4 = fabsf(f[8]-o)+fabsf(f[9]-o),  a5 = fabsf(f[10]-o)+fabsf(f[11]-o);
    float a6 = fabsf(f[12]-o)+fabsf(f[13]-o),a7 = fabsf(f[14]-o)+fabsf(f[15]-o);
    a0 += a1; a2 += a3; a4 += a5; a6 += a7;
    a0 += a2; a4 += a6;
    const float s1 = a0 + a4;

    // Green's 60-comparator sorting network (depth 10).
    cmpswap(f[0],f[1]);  cmpswap(f[2],f[3]);  cmpswap(f[4],f[5]);  cmpswap(f[6],f[7]);
    cmpswap(f[8],f[9]);  cmpswap(f[10],f[11]);cmpswap(f[12],f[13]);cmpswap(f[14],f[15]);
    cmpswap(f[0],f[2]);  cmpswap(f[1],f[3]);  cmpswap(f[4],f[6]);  cmpswap(f[5],f[7]);
    cmpswap(f[8],f[10]); cmpswap(f[9],f[11]); cmpswap(f[12],f[14]);cmpswap(f[13],f[15]);
    cmpswap(f[0],f[4]);  cmpswap(f[1],f[5]);  cmpswap(f[2],f[6]);  cmpswap(f[3],f[7]);
    cmpswap(f[8],f[12]); cmpswap(f[9],f[13]); cmpswap(f[10],f[14]);cmpswap(f[11],f[15]);
    cmpswap(f[0],f[8]);  cmpswap(f[1],f[9]);  cmpswap(f[2],f[10]); cmpswap(f[3],f[11]);
    cmpswap(f[4],f[12]); cmpswap(f[5],f[13]); cmpswap(f[6],f[14]); cmpswap(f[7],f[15]);
    cmpswap(f[5],f[10]); cmpswap(f[6],f[9]);  cmpswap(f[3],f[12]); cmpswap(f[13],f[14]);
    cmpswap(f[7],f[11]); cmpswap(f[1],f[2]);  cmpswap(f[4],f[8]);
    cmpswap(f[1],f[4]);  cmpswap(f[7],f[13]); cmpswap(f[2],f[8]);  cmpswap(f[11],f[14]);
    cmpswap(f[5],f[6]);  cmpswap(f[9],f[10]);
    cmpswap(f[2],f[4]);  cmpswap(f[11],f[13]);cmpswap(f[3],f[8]);  cmpswap(f[7],f[12]);
    cmpswap(f[6],f[8]);  cmpswap(f[10],f[12]);cmpswap(f[3],f[5]);  cmpswap(f[7],f[9]);
    cmpswap(f[3],f[4]);  cmpswap(f[5],f[6]);  cmpswap(f[7],f[8]);  cmpswap(f[9],f[10]);
    cmpswap(f[11],f[12]);
    cmpswap(f[6],f[7]);  cmpswap(f[8],f[9]);

    // sum_{e<e'} |f_e - f_{e'}| = sum_i (2i-15) f_(i)
    float s2a = 0.f, s2b = 0.f;
#pragma unroll
    for (int i = 0; i < E_; i += 2) {
        s2a = fmaf((float)(2 * i - 15), f[i], s2a);
        s2b = fmaf((float)(2 * (i + 1) - 15), f[i + 1], s2b);
    }
    const float s2 = s2a + s2b;

    const float val = fmaf(s1, 1.0f / 16.0f, -s2 * (1.0f / 256.0f));

    // ---- Deterministic in-kernel reduction ----
    const int lane = tid & 31;
    const int wid  = tid >> 5;
    float v = val;
#pragma unroll
    for (int off = 16; off > 0; off >>= 1)
        v += __shfl_down_sync(0xffffffffu, v, off);

    __shared__ float ws[TPB / 32];
    if (lane == 0) ws[wid] = v;
    __syncthreads();

    __shared__ bool is_last;
    if (wid == 0) {
        float x = (lane < TPB / 32) ? ws[lane] : 0.f;
#pragma unroll
        for (int off = 4; off > 0; off >>= 1)
            x += __shfl_down_sync(0xffffffffu, x, off);
        if (lane == 0) {
            const long long q = __double2ll_rn((double)x * FPSCALE);
            atomicAdd(&g_acc, (unsigned long long)q);
            __threadfence();
            const unsigned int tk = atomicAdd(&g_tick, 1u);
            is_last = (tk == (unsigned int)(gridDim.x - 1));
        }
    }
    __syncthreads();

    if (tid == 0 && is_last) {
        const unsigned long long tot = *((volatile unsigned long long*)&g_acc);
        const double s = (double)(long long)tot / FPSCALE;
        out[0] = (float)(s / (double)NPIX);
        g_acc  = 0ull;
        g_tick = 0u;
        __threadfence();
    }
}

extern "C" void kernel_launch(void* const* d_in, const int* in_sizes, int n_in,
                              void* d_out, int out_size) {
    const float* fore = (const float*)d_in[0];
    const float* obs  = (const float*)d_in[1];
    float* out = (float*)d_out;

    crps_tma2_kernel<<<NCTA, TPB>>>(fore, obs, out);
}

// round 16
// speedup vs baseline: 1.3592x; 1.3592x over previous
#include <cuda_runtime.h>

// Problem constants
constexpr int B_ = 8, E_ = 16, H_ = 256, W_ = 256;
constexpr int HW   = H_ * W_;        // 65536
constexpr int NPIX = B_ * HW;        // 524288
constexpr int TPB  = 256;
constexpr int NBLK = NPIX / TPB;     // 2048

// Deterministic fixed-point global accumulator (order-independent integer adds).
__device__ unsigned long long g_acc;   // zeroed at load; reset by last block each run
__device__ unsigned int       g_tick;  // block-completion counter

constexpr double FPSCALE = 4294967296.0;  // 2^32

// Comparator (FMNMX pair, alu pipe).
__device__ __forceinline__ void cmpswap(float& a, float& b) {
    const float lo = fminf(a, b);
    const float hi = fmaxf(a, b);
    a = lo; b = hi;
}

// NOTE: no min-blocks occupancy cap — let ptxas allocate ~40 regs so the
// 16-float sort working set stays fully register-resident (no local spills).
__global__ void __launch_bounds__(TPB)
crps_fused_kernel(const float* __restrict__ fore, const float* __restrict__ obs,
                  float* __restrict__ out) {
    const int g = blockIdx.x * TPB + threadIdx.x;   // pixel id
    const int b = g >> 16;                          // g / HW
    const int p = g & (HW - 1);                     // g % HW

    const float* fb = fore + ((size_t)b * E_) * HW + p;

    // 16 scalar loads with compile-time immediate offsets. MLP=16 per thread.
    float f[E_];
#pragma unroll
    for (int e = 0; e < E_; e++) f[e] = __ldg(fb + e * HW);

    const float o = __ldg(obs + g);

    // term1 numerator: tree sum of |f_e - o|   (fma pipe)
    float a0 = fabsf(f[0]-o)+fabsf(f[1]-o),  a1 = fabsf(f[2]-o)+fabsf(f[3]-o);
    float a2 = fabsf(f[4]-o)+fabsf(f[5]-o),  a3 = fabsf(f[6]-o)+fabsf(f[7]-o);
    float a4 = fabsf(f[8]-o)+fabsf(f[9]-o),  a5 = fabsf(f[10]-o)+fabsf(f[11]-o);
    float a6 = fabsf(f[12]-o)+fabsf(f[13]-o),a7 = fabsf(f[14]-o)+fabsf(f[15]-o);
    a0 += a1; a2 += a3; a4 += a5; a6 += a7;
    a0 += a2; a4 += a6;
    const float s1 = a0 + a4;

    // Green's 60-comparator sorting network for 16 elements (depth 10, alu pipe).
    cmpswap(f[0],f[1]);  cmpswap(f[2],f[3]);  cmpswap(f[4],f[5]);  cmpswap(f[6],f[7]);
    cmpswap(f[8],f[9]);  cmpswap(f[10],f[11]);cmpswap(f[12],f[13]);cmpswap(f[14],f[15]);
    cmpswap(f[0],f[2]);  cmpswap(f[1],f[3]);  cmpswap(f[4],f[6]);  cmpswap(f[5],f[7]);
    cmpswap(f[8],f[10]); cmpswap(f[9],f[11]); cmpswap(f[12],f[14]);cmpswap(f[13],f[15]);
    cmpswap(f[0],f[4]);  cmpswap(f[1],f[5]);  cmpswap(f[2],f[6]);  cmpswap(f[3],f[7]);
    cmpswap(f[8],f[12]); cmpswap(f[9],f[13]); cmpswap(f[10],f[14]);cmpswap(f[11],f[15]);
    cmpswap(f[0],f[8]);  cmpswap(f[1],f[9]);  cmpswap(f[2],f[10]); cmpswap(f[3],f[11]);
    cmpswap(f[4],f[12]); cmpswap(f[5],f[13]); cmpswap(f[6],f[14]); cmpswap(f[7],f[15]);
    cmpswap(f[5],f[10]); cmpswap(f[6],f[9]);  cmpswap(f[3],f[12]); cmpswap(f[13],f[14]);
    cmpswap(f[7],f[11]); cmpswap(f[1],f[2]);  cmpswap(f[4],f[8]);
    cmpswap(f[1],f[4]);  cmpswap(f[7],f[13]); cmpswap(f[2],f[8]);  cmpswap(f[11],f[14]);
    cmpswap(f[5],f[6]);  cmpswap(f[9],f[10]);
    cmpswap(f[2],f[4]);  cmpswap(f[11],f[13]);cmpswap(f[3],f[8]);  cmpswap(f[7],f[12]);
    cmpswap(f[6],f[8]);  cmpswap(f[10],f[12]);cmpswap(f[3],f[5]);  cmpswap(f[7],f[9]);
    cmpswap(f[3],f[4]);  cmpswap(f[5],f[6]);  cmpswap(f[7],f[8]);  cmpswap(f[9],f[10]);
    cmpswap(f[11],f[12]);
    cmpswap(f[6],f[7]);  cmpswap(f[8],f[9]);

    // sum_{e<e'} |f_e - f_{e'}| = sum_i (2i - 15) * f_(i)  (ascending), 2 chains.
    float s2a = 0.f, s2b = 0.f;
#pragma unroll
    for (int i = 0; i < E_; i += 2) {
        s2a = fmaf((float)(2 * i - 15), f[i], s2a);
        s2b = fmaf((float)(2 * (i + 1) - 15), f[i + 1], s2b);
    }
    const float s2 = s2a + s2b;

    // per-pixel contribution: term1 - 0.5*term2 = s1/16 - s2/256
    const float val = fmaf(s1, 1.0f / 16.0f, -s2 * (1.0f / 256.0f));

    // ---- Deterministic in-kernel reduction ----
    const int lane = threadIdx.x & 31;
    const int wid  = threadIdx.x >> 5;
    float v = val;
#pragma unroll
    for (int off = 16; off > 0; off >>= 1)
        v += __shfl_down_sync(0xffffffffu, v, off);

    __shared__ float ws[TPB / 32];
    if (lane == 0) ws[wid] = v;
    __syncthreads();

    __shared__ bool is_last;
    if (wid == 0) {
        float x = (lane < TPB / 32) ? ws[lane] : 0.f;
#pragma unroll
        for (int off = 4; off > 0; off >>= 1)
            x += __shfl_down_sync(0xffffffffu, x, off);
        if (lane == 0) {
            // Fixed-point -> order-independent (deterministic) global sum.
            const long long q = __double2ll_rn((double)x * FPSCALE);
            atomicAdd(&g_acc, (unsigned long long)q);
            __threadfence();
            const unsigned int tk = atomicAdd(&g_tick, 1u);
            is_last = (tk == (unsigned int)(gridDim.x - 1));
        }
    }
    __syncthreads();

    if (threadIdx.x == 0 && is_last) {
        const unsigned long long tot = *((volatile unsigned long long*)&g_acc);
        const double s = (double)(long long)tot / FPSCALE;
        out[0] = (float)(s / (double)NPIX);
        // Reset for next graph replay.
        g_acc  = 0ull;
        g_tick = 0u;
        __threadfence();
    }
}

extern "C" void kernel_launch(void* const* d_in, const int* in_sizes, int n_in,
                              void* d_out, int out_size) {
    const float* fore = (const float*)d_in[0];
    const float* obs  = (const float*)d_in[1];
    float* out = (float*)d_out;

    crps_fused_kernel<<<NBLK, TPB>>>(fore, obs, out);
}